// round 2
// baseline (speedup 1.0000x reference)
#include <cuda_runtime.h>
#include <cuda_bf16.h>
#include <cstdint>
#include <math.h>

// Problem dims
#define M_TOK 8192            // BATCH*SEQ
#define E_DIM 2048            // N_EMBD
#define F_DIM 8192            // D_FF
#define NW    16777216        // elements per weight matrix (F*E)

// ---------------- device scratch (no allocations allowed) ----------------
__device__ __nv_bfloat16 g_w1b[(size_t)F_DIM * E_DIM];
__device__ __nv_bfloat16 g_w2b[(size_t)F_DIM * E_DIM];
__device__ __nv_bfloat16 g_w3b[(size_t)E_DIM * F_DIM];
__device__ __nv_bfloat16 g_xb [(size_t)M_TOK * E_DIM];
__device__ __nv_bfloat16 g_hb [(size_t)M_TOK * F_DIM];
__device__ float  g_h  [(size_t)M_TOK * F_DIM];
__device__ float  g_inv_sx[M_TOK];
__device__ float  g_inv_sh[M_TOK];
__device__ double g_wpart[3 * 256];
__device__ float  g_wdq[3];   // dequant factor = clip(mean|w|, 1e-5)
__device__ float  g_wsc[3];   // 1/dequant

// ---------------- weight absmean (two-pass, deterministic) ----------------
__global__ void wabs_partial(const float* __restrict__ w, int n, int slot) {
    __shared__ double sd[256];
    int tid = threadIdx.x;
    double acc = 0.0;
    for (int i = blockIdx.x * 256 + tid; i < n; i += 256 * gridDim.x)
        acc += (double)fabsf(w[i]);
    sd[tid] = acc; __syncthreads();
    for (int s = 128; s > 0; s >>= 1) {
        if (tid < s) sd[tid] += sd[tid + s];
        __syncthreads();
    }
    if (tid == 0) g_wpart[slot * 256 + blockIdx.x] = sd[0];
}

__global__ void wscale_final() {
    __shared__ double sd[256];
    int tid = threadIdx.x;
    for (int wsel = 0; wsel < 3; wsel++) {
        sd[tid] = g_wpart[wsel * 256 + tid]; __syncthreads();
        for (int s = 128; s > 0; s >>= 1) {
            if (tid < s) sd[tid] += sd[tid + s];
            __syncthreads();
        }
        if (tid == 0) {
            float mean = (float)(sd[0] / (double)NW);
            float dq = fmaxf(mean, 1e-5f);
            g_wdq[wsel] = dq;
            g_wsc[wsel] = 1.0f / dq;
        }
        __syncthreads();
    }
}

// ---------------- weight ternary quantization -> bf16 {-1,0,1} ----------------
__global__ void quant_w(const float* __restrict__ w, __nv_bfloat16* __restrict__ q,
                        int n, int wi) {
    float s = g_wsc[wi];
    int i = (blockIdx.x * blockDim.x + threadIdx.x) * 4;
    if (i < n) {
        float4 v = *(const float4*)(w + i);
        float a = fminf(fmaxf(rintf(v.x * s), -1.0f), 1.0f);
        float b = fminf(fmaxf(rintf(v.y * s), -1.0f), 1.0f);
        float c = fminf(fmaxf(rintf(v.z * s), -1.0f), 1.0f);
        float d = fminf(fmaxf(rintf(v.w * s), -1.0f), 1.0f);
        ushort4 o;
        o.x = __bfloat16_as_ushort(__float2bfloat16_rn(a));
        o.y = __bfloat16_as_ushort(__float2bfloat16_rn(b));
        o.z = __bfloat16_as_ushort(__float2bfloat16_rn(c));
        o.w = __bfloat16_as_ushort(__float2bfloat16_rn(d));
        *(ushort4*)(q + i) = o;
    }
}

// ---------------- rmsnorm + per-token absmax int8 quant -> bf16 integers ----------------
template <int VE>
__global__ void act_quant(const float* __restrict__ in, __nv_bfloat16* __restrict__ q,
                          float* __restrict__ inv, int rowlen) {
    int m = blockIdx.x, tid = threadIdx.x;
    const float4* row = (const float4*)(in + (size_t)m * rowlen);
    float4 v[VE / 4];
    float ss = 0.0f, mx = 0.0f;
#pragma unroll
    for (int j = 0; j < VE / 4; j++) {
        v[j] = row[tid + j * 256];
        ss += v[j].x * v[j].x + v[j].y * v[j].y + v[j].z * v[j].z + v[j].w * v[j].w;
        mx = fmaxf(mx, fmaxf(fmaxf(fabsf(v[j].x), fabsf(v[j].y)),
                             fmaxf(fabsf(v[j].z), fabsf(v[j].w))));
    }
    __shared__ float sss[256], smx[256];
    sss[tid] = ss; smx[tid] = mx; __syncthreads();
    for (int s = 128; s > 0; s >>= 1) {
        if (tid < s) {
            sss[tid] += sss[tid + s];
            smx[tid] = fmaxf(smx[tid], smx[tid + s]);
        }
        __syncthreads();
    }
    float r = rsqrtf(sss[0] / (float)rowlen + 1e-6f);   // rmsnorm (eps=1e-6)
    float cmax = fmaxf(smx[0] * r, 1e-5f);              // clip(max|xn|, EPS=1e-5)
    float scale = 127.0f / cmax;
    if (tid == 0) inv[m] = cmax / 127.0f;               // dequant factor

    ushort4* qrow = (ushort4*)(q + (size_t)m * rowlen);
#pragma unroll
    for (int j = 0; j < VE / 4; j++) {
        int qx = __float2int_rn(v[j].x * r * scale);
        int qy = __float2int_rn(v[j].y * r * scale);
        int qz = __float2int_rn(v[j].z * r * scale);
        int qw = __float2int_rn(v[j].w * r * scale);
        qx = min(max(qx, -128), 127);
        qy = min(max(qy, -128), 127);
        qz = min(max(qz, -128), 127);
        qw = min(max(qw, -128), 127);
        ushort4 o;   // small integers are exact in bf16
        o.x = __bfloat16_as_ushort(__float2bfloat16_rn((float)qx));
        o.y = __bfloat16_as_ushort(__float2bfloat16_rn((float)qy));
        o.z = __bfloat16_as_ushort(__float2bfloat16_rn((float)qz));
        o.w = __bfloat16_as_ushort(__float2bfloat16_rn((float)qw));
        qrow[tid + j * 256] = o;
    }
}

// ---------------- bf16 tensor-core GEMM (mma.sync m16n8k16, exact int math) ----------------
#define BM 128
#define BN 128
#define BKE 64            // K elements per tile
#define SROW 144          // padded smem row stride in bytes (128 data + 16 pad)
#define TILEB (128 * SROW)

__device__ __forceinline__ void cp16(void* sdst, const void* gsrc) {
    unsigned s = (unsigned)__cvta_generic_to_shared(sdst);
    asm volatile("cp.async.cg.shared.global [%0], [%1], 16;\n" :: "r"(s), "l"(gsrc) : "memory");
}
__device__ __forceinline__ void cp_commit() { asm volatile("cp.async.commit_group;\n" ::: "memory"); }
__device__ __forceinline__ void cp_wait0()  { asm volatile("cp.async.wait_group 0;\n" ::: "memory"); }

__device__ __forceinline__ void mma_bf16(float* c, const unsigned* a, const unsigned* b) {
    asm volatile(
        "mma.sync.aligned.m16n8k16.row.col.f32.bf16.bf16.f32 "
        "{%0,%1,%2,%3},{%4,%5,%6,%7},{%8,%9},{%0,%1,%2,%3};\n"
        : "+f"(c[0]), "+f"(c[1]), "+f"(c[2]), "+f"(c[3])
        : "r"(a[0]), "r"(a[1]), "r"(a[2]), "r"(a[3]), "r"(b[0]), "r"(b[1]));
}

template <bool DUAL>
__global__ void __launch_bounds__(256, 1) gemm_bf(
    const __nv_bfloat16* __restrict__ A,
    const __nv_bfloat16* __restrict__ B1,
    const __nv_bfloat16* __restrict__ B2,
    int K, const float* __restrict__ invA, int wi1, int wi2,
    float* __restrict__ out, int ldo)
{
    extern __shared__ char smem[];
    const int TB = (DUAL ? 3 : 2) * TILEB;
    int tid = threadIdx.x;
    int m0 = blockIdx.y * BM, n0 = blockIdx.x * BN;
    size_t Kb = (size_t)K * 2;                 // row stride in bytes
    const char* Ab  = (const char*)A  + (size_t)m0 * Kb;
    const char* B1b = (const char*)B1 + (size_t)n0 * Kb;
    const char* B2b = DUAL ? ((const char*)B2 + (size_t)n0 * Kb) : nullptr;
    int KT = K / BKE;

    auto issue = [&](int kt, int buf) {
        char* base = smem + buf * TB;
        size_t k0b = (size_t)kt * BKE * 2;
#pragma unroll
        for (int it = 0; it < 4; it++) {
            int c = it * 256 + tid;
            int row = c >> 3;
            int col = (c & 7) * 16;
            cp16(base + row * SROW + col,             Ab  + (size_t)row * Kb + k0b + col);
            cp16(base + TILEB + row * SROW + col,     B1b + (size_t)row * Kb + k0b + col);
            if (DUAL)
                cp16(base + 2 * TILEB + row * SROW + col, B2b + (size_t)row * Kb + k0b + col);
        }
        cp_commit();
    };

    int wid = tid >> 5, lane = tid & 31;
    int wm = wid >> 2, wn = wid & 3;     // warps: 2 (M) x 4 (N); warp tile 64x32
    int g = lane >> 2, t4 = lane & 3;

    float c1[4][4][4] = {};
    float c2[4][4][4] = {};

    issue(0, 0);
    for (int kt = 0; kt < KT; kt++) {
        cp_wait0();
        __syncthreads();
        if (kt + 1 < KT) issue(kt + 1, (kt + 1) & 1);

        const char* base = smem + (kt & 1) * TB;
        const char* Asm  = base;
        const char* B1sm = base + TILEB;
        const char* B2sm = base + 2 * TILEB;

#pragma unroll
        for (int ks = 0; ks < BKE; ks += 16) {      // one m16n8k16 step per 16 elements
            int kb = ks * 2;                        // byte offset
            unsigned a[4][4];
#pragma unroll
            for (int im = 0; im < 4; im++) {
                const char* p = Asm + (wm * 64 + im * 16 + g) * SROW + kb + t4 * 4;
                a[im][0] = *(const unsigned*)p;                  // (g,   k0..7)
                a[im][1] = *(const unsigned*)(p + 8 * SROW);     // (g+8, k0..7)
                a[im][2] = *(const unsigned*)(p + 16);           // (g,   k8..15)
                a[im][3] = *(const unsigned*)(p + 8 * SROW + 16);// (g+8, k8..15)
            }
#pragma unroll
            for (int in = 0; in < 4; in++) {
                const char* p = B1sm + (wn * 32 + in * 8 + g) * SROW + kb + t4 * 4;
                unsigned b[2] = { *(const unsigned*)p, *(const unsigned*)(p + 16) };
#pragma unroll
                for (int im = 0; im < 4; im++) mma_bf16(c1[im][in], a[im], b);
                if constexpr (DUAL) {
                    const char* p2 = B2sm + (wn * 32 + in * 8 + g) * SROW + kb + t4 * 4;
                    unsigned b2[2] = { *(const unsigned*)p2, *(const unsigned*)(p2 + 16) };
#pragma unroll
                    for (int im = 0; im < 4; im++) mma_bf16(c2[im][in], a[im], b2);
                }
            }
        }
    }

    // epilogue: dequant (+ SwiGLU combine for DUAL). c values are exact integers.
    float dq1 = g_wdq[wi1];
    float dq2 = DUAL ? g_wdq[wi2] : 0.0f;
#pragma unroll
    for (int im = 0; im < 4; im++) {
#pragma unroll
        for (int h2 = 0; h2 < 2; h2++) {
            int row = m0 + wm * 64 + im * 16 + g + h2 * 8;
            float ia = invA[row];
#pragma unroll
            for (int in = 0; in < 4; in++) {
                int col = n0 + wn * 32 + in * 8 + t4 * 2;
                size_t o = (size_t)row * ldo + col;
                if constexpr (DUAL) {
                    float f1a = c1[im][in][h2 * 2 + 0] * ia * dq1;
                    float f1b = c1[im][in][h2 * 2 + 1] * ia * dq1;
                    float f2a = c2[im][in][h2 * 2 + 0] * ia * dq2;
                    float f2b = c2[im][in][h2 * 2 + 1] * ia * dq2;
                    out[o]     = f1a / (1.0f + expf(-f1a)) * f2a;   // silu(g1)*g2
                    out[o + 1] = f1b / (1.0f + expf(-f1b)) * f2b;
                } else {
                    out[o]     = c1[im][in][h2 * 2 + 0] * ia * dq1;
                    out[o + 1] = c1[im][in][h2 * 2 + 1] * ia * dq1;
                }
            }
        }
    }
}

// ---------------- launch ----------------
extern "C" void kernel_launch(void* const* d_in, const int* in_sizes, int n_in,
                              void* d_out, int out_size) {
    const float* x  = (const float*)d_in[0];
    const float* w1 = (const float*)d_in[1];
    const float* w2 = (const float*)d_in[2];
    const float* w3 = (const float*)d_in[3];
    float* out = (float*)d_out;

    void *p_w1b, *p_w2b, *p_w3b, *p_xb, *p_hb, *p_h, *p_isx, *p_ish;
    cudaGetSymbolAddress(&p_w1b, g_w1b);
    cudaGetSymbolAddress(&p_w2b, g_w2b);
    cudaGetSymbolAddress(&p_w3b, g_w3b);
    cudaGetSymbolAddress(&p_xb,  g_xb);
    cudaGetSymbolAddress(&p_hb,  g_hb);
    cudaGetSymbolAddress(&p_h,   g_h);
    cudaGetSymbolAddress(&p_isx, g_inv_sx);
    cudaGetSymbolAddress(&p_ish, g_inv_sh);

    cudaFuncSetAttribute(gemm_bf<true>,  cudaFuncAttributeMaxDynamicSharedMemorySize, 2 * 3 * TILEB);
    cudaFuncSetAttribute(gemm_bf<false>, cudaFuncAttributeMaxDynamicSharedMemorySize, 2 * 2 * TILEB);

    // 1) weight scales (absmean, deterministic two-pass)
    wabs_partial<<<256, 256>>>(w1, NW, 0);
    wabs_partial<<<256, 256>>>(w2, NW, 1);
    wabs_partial<<<256, 256>>>(w3, NW, 2);
    wscale_final<<<1, 256>>>();

    // 2) ternary weight quantization (bf16 {-1,0,1})
    quant_w<<<NW / 1024, 256>>>(w1, (__nv_bfloat16*)p_w1b, NW, 0);
    quant_w<<<NW / 1024, 256>>>(w2, (__nv_bfloat16*)p_w2b, NW, 1);
    quant_w<<<NW / 1024, 256>>>(w3, (__nv_bfloat16*)p_w3b, NW, 2);

    // 3) rmsnorm + int8-grid quant of x (stored bf16)
    act_quant<8><<<M_TOK, 256>>>(x, (__nv_bfloat16*)p_xb, (float*)p_isx, E_DIM);

    // 4) fused dual GEMM (w1,w2) + SwiGLU -> h (fp32)
    gemm_bf<true><<<dim3(F_DIM / BN, M_TOK / BM), 256, 2 * 3 * TILEB>>>(
        (const __nv_bfloat16*)p_xb, (const __nv_bfloat16*)p_w1b, (const __nv_bfloat16*)p_w2b,
        E_DIM, (const float*)p_isx, 0, 1, (float*)p_h, F_DIM);

    // 5) rmsnorm + int8-grid quant of h (stored bf16)
    act_quant<32><<<M_TOK, 256>>>((const float*)p_h, (__nv_bfloat16*)p_hb, (float*)p_ish, F_DIM);

    // 6) GEMM2 (w3) -> out
    gemm_bf<false><<<dim3(E_DIM / BN, M_TOK / BM), 256, 2 * 2 * TILEB>>>(
        (const __nv_bfloat16*)p_hb, (const __nv_bfloat16*)p_w3b, nullptr,
        F_DIM, (const float*)p_ish, 2, 2, out, E_DIM);
}

// round 4
// speedup vs baseline: 1.0436x; 1.0436x over previous
#include <cuda_runtime.h>
#include <cuda_bf16.h>
#include <cstdint>
#include <math.h>

// Problem dims
#define M_TOK 8192
#define E_DIM 2048
#define F_DIM 8192
#define NW    16777216

// ---------------- device scratch ----------------
__device__ __nv_bfloat16 g_w1b[(size_t)F_DIM * E_DIM];
__device__ __nv_bfloat16 g_w2b[(size_t)F_DIM * E_DIM];
__device__ __nv_bfloat16 g_w3b[(size_t)E_DIM * F_DIM];
__device__ __nv_bfloat16 g_xb [(size_t)M_TOK * E_DIM];
__device__ __nv_bfloat16 g_hb [(size_t)M_TOK * F_DIM];
__device__ float  g_h  [(size_t)M_TOK * F_DIM];
__device__ float  g_inv_sx[M_TOK];
__device__ float  g_inv_sh[M_TOK];
__device__ double g_wpart[3 * 256];
__device__ float  g_wdq[3];
__device__ float  g_wsc[3];

// ---------------- prep kernels (unchanged, known correct) ----------------
__global__ void wabs_partial(const float* __restrict__ w, int n, int slot) {
    __shared__ double sd[256];
    int tid = threadIdx.x;
    double acc = 0.0;
    for (int i = blockIdx.x * 256 + tid; i < n; i += 256 * gridDim.x)
        acc += (double)fabsf(w[i]);
    sd[tid] = acc; __syncthreads();
    for (int s = 128; s > 0; s >>= 1) {
        if (tid < s) sd[tid] += sd[tid + s];
        __syncthreads();
    }
    if (tid == 0) g_wpart[slot * 256 + blockIdx.x] = sd[0];
}

__global__ void wscale_final() {
    __shared__ double sd[256];
    int tid = threadIdx.x;
    for (int wsel = 0; wsel < 3; wsel++) {
        sd[tid] = g_wpart[wsel * 256 + tid]; __syncthreads();
        for (int s = 128; s > 0; s >>= 1) {
            if (tid < s) sd[tid] += sd[tid + s];
            __syncthreads();
        }
        if (tid == 0) {
            float mean = (float)(sd[0] / (double)NW);
            float dq = fmaxf(mean, 1e-5f);
            g_wdq[wsel] = dq;
            g_wsc[wsel] = 1.0f / dq;
        }
        __syncthreads();
    }
}

__global__ void quant_w(const float* __restrict__ w, __nv_bfloat16* __restrict__ q,
                        int n, int wi) {
    float s = g_wsc[wi];
    int i = (blockIdx.x * blockDim.x + threadIdx.x) * 4;
    if (i < n) {
        float4 v = *(const float4*)(w + i);
        ushort4 o;
        o.x = __bfloat16_as_ushort(__float2bfloat16_rn(fminf(fmaxf(rintf(v.x * s), -1.0f), 1.0f)));
        o.y = __bfloat16_as_ushort(__float2bfloat16_rn(fminf(fmaxf(rintf(v.y * s), -1.0f), 1.0f)));
        o.z = __bfloat16_as_ushort(__float2bfloat16_rn(fminf(fmaxf(rintf(v.z * s), -1.0f), 1.0f)));
        o.w = __bfloat16_as_ushort(__float2bfloat16_rn(fminf(fmaxf(rintf(v.w * s), -1.0f), 1.0f)));
        *(ushort4*)(q + i) = o;
    }
}

template <int VE>
__global__ void act_quant(const float* __restrict__ in, __nv_bfloat16* __restrict__ q,
                          float* __restrict__ inv, int rowlen) {
    int m = blockIdx.x, tid = threadIdx.x;
    const float4* row = (const float4*)(in + (size_t)m * rowlen);
    float4 v[VE / 4];
    float ss = 0.0f, mx = 0.0f;
#pragma unroll
    for (int j = 0; j < VE / 4; j++) {
        v[j] = row[tid + j * 256];
        ss += v[j].x * v[j].x + v[j].y * v[j].y + v[j].z * v[j].z + v[j].w * v[j].w;
        mx = fmaxf(mx, fmaxf(fmaxf(fabsf(v[j].x), fabsf(v[j].y)),
                             fmaxf(fabsf(v[j].z), fabsf(v[j].w))));
    }
    __shared__ float sss[256], smx[256];
    sss[tid] = ss; smx[tid] = mx; __syncthreads();
    for (int s = 128; s > 0; s >>= 1) {
        if (tid < s) {
            sss[tid] += sss[tid + s];
            smx[tid] = fmaxf(smx[tid], smx[tid + s]);
        }
        __syncthreads();
    }
    float r = rsqrtf(sss[0] / (float)rowlen + 1e-6f);
    float cmax = fmaxf(smx[0] * r, 1e-5f);
    float scale = 127.0f / cmax;
    if (tid == 0) inv[m] = cmax / 127.0f;

    ushort4* qrow = (ushort4*)(q + (size_t)m * rowlen);
#pragma unroll
    for (int j = 0; j < VE / 4; j++) {
        int qx = __float2int_rn(v[j].x * r * scale);
        int qy = __float2int_rn(v[j].y * r * scale);
        int qz = __float2int_rn(v[j].z * r * scale);
        int qw = __float2int_rn(v[j].w * r * scale);
        qx = min(max(qx, -128), 127); qy = min(max(qy, -128), 127);
        qz = min(max(qz, -128), 127); qw = min(max(qw, -128), 127);
        ushort4 o;
        o.x = __bfloat16_as_ushort(__float2bfloat16_rn((float)qx));
        o.y = __bfloat16_as_ushort(__float2bfloat16_rn((float)qy));
        o.z = __bfloat16_as_ushort(__float2bfloat16_rn((float)qz));
        o.w = __bfloat16_as_ushort(__float2bfloat16_rn((float)qw));
        qrow[tid + j * 256] = o;
    }
}

// ---------------- bf16 mma.sync GEMM with ldmatrix + 3-stage cp.async ----------------
#define BM 128
#define BN 128
#define BKE 64            // K elements per tile (128 bytes per row)
#define SROW 144          // padded smem row stride in bytes
#define TILEB (128 * SROW)
#define NSTG 3

__device__ __forceinline__ uint32_t smem_u32(const void* p) {
    uint32_t a;
    asm("{ .reg .u64 t; cvta.to.shared.u64 t, %1; cvt.u32.u64 %0, t; }" : "=r"(a) : "l"(p));
    return a;
}
__device__ __forceinline__ void cp16(uint32_t sdst, const void* gsrc) {
    asm volatile("cp.async.cg.shared.global [%0], [%1], 16;\n" :: "r"(sdst), "l"(gsrc) : "memory");
}
__device__ __forceinline__ void cp_commit() { asm volatile("cp.async.commit_group;\n" ::: "memory"); }
__device__ __forceinline__ void cp_wait0()  { asm volatile("cp.async.wait_group 0;\n" ::: "memory"); }
__device__ __forceinline__ void cp_wait1()  { asm volatile("cp.async.wait_group 1;\n" ::: "memory"); }

__device__ __forceinline__ void ldsm4(uint32_t* r, uint32_t addr) {
    asm volatile("ldmatrix.sync.aligned.m8n8.x4.shared.b16 {%0,%1,%2,%3}, [%4];"
        : "=r"(r[0]), "=r"(r[1]), "=r"(r[2]), "=r"(r[3]) : "r"(addr));
}
__device__ __forceinline__ void mma_bf16(float* c, const uint32_t* a, const uint32_t* b) {
    asm volatile(
        "mma.sync.aligned.m16n8k16.row.col.f32.bf16.bf16.f32 "
        "{%0,%1,%2,%3},{%4,%5,%6,%7},{%8,%9},{%0,%1,%2,%3};\n"
        : "+f"(c[0]), "+f"(c[1]), "+f"(c[2]), "+f"(c[3])
        : "r"(a[0]), "r"(a[1]), "r"(a[2]), "r"(a[3]), "r"(b[0]), "r"(b[1]));
}

template <bool DUAL>
__global__ void __launch_bounds__(256, 1) gemm_bf(
    const __nv_bfloat16* __restrict__ A,
    const __nv_bfloat16* __restrict__ B1,
    const __nv_bfloat16* __restrict__ B2,
    int K, const float* __restrict__ invA, int wi1, int wi2,
    float* __restrict__ out, int ldo)
{
    extern __shared__ char smem[];
    const int TB = (DUAL ? 3 : 2) * TILEB;
    const uint32_t sb = smem_u32(smem);
    int tid = threadIdx.x;
    int m0 = blockIdx.y * BM, n0 = blockIdx.x * BN;
    size_t Kb = (size_t)K * 2;
    const char* Ab  = (const char*)A  + (size_t)m0 * Kb;
    const char* B1b = (const char*)B1 + (size_t)n0 * Kb;
    const char* B2b = DUAL ? ((const char*)B2 + (size_t)n0 * Kb) : nullptr;
    int KT = K / BKE;

    // cp.async producer (all threads): one commit group per k-tile
    auto issue = [&](int kt) {
        uint32_t base = sb + (kt % NSTG) * TB;
        size_t k0b = (size_t)kt * BKE * 2;
#pragma unroll
        for (int it = 0; it < 4; it++) {
            int c = it * 256 + tid;
            int row = c >> 3;
            int col = (c & 7) * 16;
            uint32_t soff = (uint32_t)(row * SROW + col);
            cp16(base + soff,             Ab  + (size_t)row * Kb + k0b + col);
            cp16(base + TILEB + soff,     B1b + (size_t)row * Kb + k0b + col);
            if (DUAL)
                cp16(base + 2 * TILEB + soff, B2b + (size_t)row * Kb + k0b + col);
        }
        cp_commit();
    };

    int wid = tid >> 5, lane = tid & 31;
    int wm = wid >> 2, wn = wid & 3;     // warps: 2 (M) x 4 (N); warp tile 64x32
    int g = lane >> 2, t4 = lane & 3;

    // ldmatrix per-lane offsets (within a tile)
    // A x4 (16 rows x 16 k): lanes 0-15 -> rows 0-15 @k0; 16-31 -> rows 0-15 @+16B
    uint32_t offA[4];
#pragma unroll
    for (int im = 0; im < 4; im++)
        offA[im] = (uint32_t)((wm * 64 + im * 16 + (lane & 15)) * SROW + (lane >> 4) * 16);
    // B x4 (16 n x 16 k): lanes 0-7 n0-7@k0, 8-15 n0-7@+16B, 16-23 n8-15@k0, 24-31 n8-15@+16B
    uint32_t offB[2];
#pragma unroll
    for (int ib = 0; ib < 2; ib++)
        offB[ib] = (uint32_t)((wn * 32 + ib * 16 + (lane & 7) + ((lane >> 4) & 1) * 8) * SROW
                              + ((lane >> 3) & 1) * 16);

    float c1[4][4][4] = {};
    float c2[4][4][4] = {};

    issue(0);
    issue(1);
    for (int kt = 0; kt < KT; kt++) {
        if (kt == KT - 1) cp_wait0(); else cp_wait1();
        __syncthreads();
        if (kt + 2 < KT) issue(kt + 2);

        const uint32_t base = sb + (kt % NSTG) * TB;
        const uint32_t AsmB = base, B1sm = base + TILEB, B2sm = base + 2 * TILEB;

#pragma unroll
        for (int ks = 0; ks < 4; ks++) {            // 16 K-elems per step
            const uint32_t kb = ks * 32;            // bytes
            uint32_t a[4][4];
#pragma unroll
            for (int im = 0; im < 4; im++) ldsm4(a[im], AsmB + offA[im] + kb);

            uint32_t b1[2][4];
#pragma unroll
            for (int ib = 0; ib < 2; ib++) ldsm4(b1[ib], B1sm + offB[ib] + kb);
#pragma unroll
            for (int ib = 0; ib < 2; ib++)
#pragma unroll
                for (int sub = 0; sub < 2; sub++)
#pragma unroll
                    for (int im = 0; im < 4; im++)
                        mma_bf16(c1[im][ib * 2 + sub], a[im], &b1[ib][sub * 2]);

            if constexpr (DUAL) {
                uint32_t b2[2][4];
#pragma unroll
                for (int ib = 0; ib < 2; ib++) ldsm4(b2[ib], B2sm + offB[ib] + kb);
#pragma unroll
                for (int ib = 0; ib < 2; ib++)
#pragma unroll
                    for (int sub = 0; sub < 2; sub++)
#pragma unroll
                        for (int im = 0; im < 4; im++)
                            mma_bf16(c2[im][ib * 2 + sub], a[im], &b2[ib][sub * 2]);
            }
        }
        __syncthreads();
    }

    // epilogue: dequant (+ SwiGLU for DUAL). Accumulators are exact integers.
    float dq1 = g_wdq[wi1];
    float dq2 = DUAL ? g_wdq[wi2] : 0.0f;
#pragma unroll
    for (int im = 0; im < 4; im++) {
#pragma unroll
        for (int h2 = 0; h2 < 2; h2++) {
            int row = m0 + wm * 64 + im * 16 + g + h2 * 8;
            float ia = invA[row];
#pragma unroll
            for (int in = 0; in < 4; in++) {
                int col = n0 + wn * 32 + in * 8 + t4 * 2;
                size_t o = (size_t)row * ldo + col;
                if constexpr (DUAL) {
                    float f1a = c1[im][in][h2 * 2 + 0] * ia * dq1;
                    float f1b = c1[im][in][h2 * 2 + 1] * ia * dq1;
                    float f2a = c2[im][in][h2 * 2 + 0] * ia * dq2;
                    float f2b = c2[im][in][h2 * 2 + 1] * ia * dq2;
                    out[o]     = f1a / (1.0f + expf(-f1a)) * f2a;
                    out[o + 1] = f1b / (1.0f + expf(-f1b)) * f2b;
                } else {
                    out[o]     = c1[im][in][h2 * 2 + 0] * ia * dq1;
                    out[o + 1] = c1[im][in][h2 * 2 + 1] * ia * dq1;
                }
            }
        }
    }
}

// ---------------- launch ----------------
extern "C" void kernel_launch(void* const* d_in, const int* in_sizes, int n_in,
                              void* d_out, int out_size) {
    const float* x  = (const float*)d_in[0];
    const float* w1 = (const float*)d_in[1];
    const float* w2 = (const float*)d_in[2];
    const float* w3 = (const float*)d_in[3];
    float* out = (float*)d_out;

    void *p_w1b, *p_w2b, *p_w3b, *p_xb, *p_hb, *p_h, *p_isx, *p_ish;
    cudaGetSymbolAddress(&p_w1b, g_w1b);
    cudaGetSymbolAddress(&p_w2b, g_w2b);
    cudaGetSymbolAddress(&p_w3b, g_w3b);
    cudaGetSymbolAddress(&p_xb,  g_xb);
    cudaGetSymbolAddress(&p_hb,  g_hb);
    cudaGetSymbolAddress(&p_h,   g_h);
    cudaGetSymbolAddress(&p_isx, g_inv_sx);
    cudaGetSymbolAddress(&p_ish, g_inv_sh);

    const int SM1 = NSTG * 3 * TILEB;   // dual:   3 stages * 54KB = 162KB
    const int SM2 = NSTG * 2 * TILEB;   // single: 3 stages * 36KB = 108KB
    cudaFuncSetAttribute(gemm_bf<true>,  cudaFuncAttributeMaxDynamicSharedMemorySize, SM1);
    cudaFuncSetAttribute(gemm_bf<false>, cudaFuncAttributeMaxDynamicSharedMemorySize, SM2);

    // 1) weight scales
    wabs_partial<<<256, 256>>>(w1, NW, 0);
    wabs_partial<<<256, 256>>>(w2, NW, 1);
    wabs_partial<<<256, 256>>>(w3, NW, 2);
    wscale_final<<<1, 256>>>();

    // 2) ternary weight quantization (bf16 {-1,0,1})
    quant_w<<<NW / 1024, 256>>>(w1, (__nv_bfloat16*)p_w1b, NW, 0);
    quant_w<<<NW / 1024, 256>>>(w2, (__nv_bfloat16*)p_w2b, NW, 1);
    quant_w<<<NW / 1024, 256>>>(w3, (__nv_bfloat16*)p_w3b, NW, 2);

    // 3) rmsnorm + int8-grid quant of x (stored bf16)
    act_quant<8><<<M_TOK, 256>>>(x, (__nv_bfloat16*)p_xb, (float*)p_isx, E_DIM);

    // 4) fused dual GEMM (w1,w2) + SwiGLU -> h (fp32)
    gemm_bf<true><<<dim3(F_DIM / BN, M_TOK / BM), 256, SM1>>>(
        (const __nv_bfloat16*)p_xb, (const __nv_bfloat16*)p_w1b, (const __nv_bfloat16*)p_w2b,
        E_DIM, (const float*)p_isx, 0, 1, (float*)p_h, F_DIM);

    // 5) rmsnorm + int8-grid quant of h (stored bf16)
    act_quant<32><<<M_TOK, 256>>>((const float*)p_h, (__nv_bfloat16*)p_hb, (float*)p_ish, F_DIM);

    // 6) GEMM2 (w3) -> out
    gemm_bf<false><<<dim3(E_DIM / BN, M_TOK / BM), 256, SM2>>>(
        (const __nv_bfloat16*)p_hb, (const __nv_bfloat16*)p_w3b, nullptr,
        F_DIM, (const float*)p_ish, 2, 2, out, E_DIM);
}